// round 4
// baseline (speedup 1.0000x reference)
#include <cuda_runtime.h>

#define TPB 512
#define NLAYER 4
#define LN_EPS 1e-5f

// ~95.4 KB shared per block -> 2 blocks/SM (grid=256 over 148 SMs, 32 warps/SM).
struct __align__(16) Smem {
    float R[NLAYER][32][32];        // conv_root
    float W[NLAYER][3][32][32];     // conv_w
    float bias[NLAYER][32];         // conv_bias
    float Wf[6][32];                // W_f
    float bf[32];
    float lng[32];
    float lnb[32];
    float xs[64][33];               // node features, stride 33
    float Lij[16][33];              // line sums over k, rows (i*4+j)
    float Lik[16][33];              // line sums over j, rows (i*4+k)
    float Si[4][33];                // plane sums over (j,k)
    float Sj[4][33];                // plane sums over (i,k)
    float Sk[4][33];                // plane sums over (i,j)
    float AW[3][16][36];            // agg_r @ W_r   (stride 36 -> float4 ok)
    float Hroot[64][36];            // x @ R         (stride 36 -> float4 ok)
    float zero[36];                 // uniform zero operand for root rows
};

__global__ __launch_bounds__(TPB, 2) void gnn_frame0_kernel(
    const float* __restrict__ xx, const float* __restrict__ ss,
    const float* __restrict__ W_f, const float* __restrict__ b_f,
    const float* __restrict__ conv_w, const float* __restrict__ conv_root,
    const float* __restrict__ conv_bias, const float* __restrict__ ln_g,
    const float* __restrict__ ln_b, float* __restrict__ out)
{
    extern __shared__ __align__(16) unsigned char smem_raw[];
    Smem* s = reinterpret_cast<Smem*>(smem_raw);
    const int tid = threadIdx.x;
    const int b = blockIdx.x;

    // ---- stage weights (float4, coalesced; all warps participate) ----
    {
        // R (1024 f4) + W (3072 f4) = 4096 float4, one contiguous region.
        float4*       dRW = reinterpret_cast<float4*>(&s->R[0][0][0]);
        const float4* gR  = reinterpret_cast<const float4*>(conv_root);
        const float4* gW  = reinterpret_cast<const float4*>(conv_w);
        #pragma unroll
        for (int i = tid; i < 4096; i += TPB)
            dRW[i] = (i < 1024) ? gR[i] : gW[i - 1024];
        // small tables: 32+48 float4 + 3*32 scalars + 36 zeros, one pass
        if (tid < 32) {
            reinterpret_cast<float4*>(&s->bias[0][0])[tid] =
                reinterpret_cast<const float4*>(conv_bias)[tid];
        } else if (tid < 80) {
            reinterpret_cast<float4*>(&s->Wf[0][0])[tid - 32] =
                reinterpret_cast<const float4*>(W_f)[tid - 32];
        } else if (tid < 112) {
            s->bf[tid - 80] = b_f[tid - 80];
        } else if (tid < 144) {
            s->lng[tid - 112] = ln_g[tid - 112];
        } else if (tid < 176) {
            s->lnb[tid - 144] = ln_b[tid - 144];
        } else if (tid < 212) {
            s->zero[tid - 176] = 0.0f;
        }
    }

    // thread -> (node, 4-channel group) for init / combine phases
    const int nd  = tid >> 3;          // 0..63
    const int ch0 = (tid & 7) * 4;     // 0,4,...,28
    const int ii = nd >> 4, jj = (nd >> 2) & 3, kk = nd & 3;
    const int rij = (ii << 2) | jj;
    const int rik = (ii << 2) | kk;

    __syncthreads();

    // ---- initial features (frame t=0): x0 = feats @ W_f + b_f ----
    {
        const float fi = ii * (1.0f / 3.0f);
        const float fj = jj * (1.0f / 3.0f);
        const float fk = kk * (1.0f / 3.0f);
        const float v  = xx[b * 512 + nd];   // frame 0 = first 64 nodes
        const float m  = ss[b] * 0.125f;     // ss / T
        #pragma unroll
        for (int q = 0; q < 4; q++) {
            int c = ch0 + q;
            s->xs[nd][c] = s->bf[c] + fi * s->Wf[0][c] + fj * s->Wf[1][c]
                         + fk * s->Wf[2][c] + v * s->Wf[4][c] + m * s->Wf[5][c];
        }
    }
    __syncthreads();

    // ---- matmul-phase mapping: 112 rows x 4 quarter-groups = 448 threads ----
    const int row = tid >> 2;          // 0..111 (for tid < 448)
    const int cc  = (tid & 3) * 8;     // 0,8,16,24
    const float* opA = s->zero;
    const float* opB = s->zero;
    float* dst = s->zero;              // inactive threads never store
    float scale = 0.0f;
    int  wOff = 0;
    bool rootRow = false;
    if (tid < 448) {
        if (row < 48) {
            int r = row >> 4, sr = row & 15;
            wOff = r * 1024;
            dst  = &s->AW[r][sr][cc];
            opB  = (r == 2) ? s->Lik[sr] : s->Lij[sr];
            opA  = (r == 0) ? s->Si[sr >> 2] : (r == 1 ? s->Sj[sr & 3] : s->Sk[sr & 3]);
            scale = 1.0f / 12.0f;
        } else {
            int n2 = row - 48;
            dst  = &s->Hroot[n2][cc];
            opA  = s->xs[n2];
            scale = 1.0f;
            rootRow = true;
        }
    }

    // ---- 4 R-GCN layers ----
    for (int l = 0; l < NLAYER; l++) {
        // Phase A: line sums (512 items) + plane sums (384 items), one sync.
        {
            int rr = tid >> 5, c = tid & 31;   // tid covers all 512
            s->Lij[rr][c] = s->xs[rr * 4 + 0][c] + s->xs[rr * 4 + 1][c]
                          + s->xs[rr * 4 + 2][c] + s->xs[rr * 4 + 3][c];
            int base = (rr >> 2) * 16 + (rr & 3);
            s->Lik[rr][c] = s->xs[base][c] + s->xs[base + 4][c]
                          + s->xs[base + 8][c] + s->xs[base + 12][c];
        }
        if (tid < 384) {
            int which = tid >> 7, idx = (tid >> 5) & 3, c = tid & 31;
            float acc = 0.0f;
            if (which == 0) {          // Si[i] = sum over (j,k)
                #pragma unroll
                for (int m = 0; m < 16; m++) acc += s->xs[idx * 16 + m][c];
                s->Si[idx][c] = acc;
            } else if (which == 1) {   // Sj[j] = sum over (i,k)
                #pragma unroll
                for (int i2 = 0; i2 < 4; i2++)
                    #pragma unroll
                    for (int k2 = 0; k2 < 4; k2++)
                        acc += s->xs[i2 * 16 + idx * 4 + k2][c];
                s->Sj[idx][c] = acc;
            } else {                   // Sk[k] = sum over (i,j)
                #pragma unroll
                for (int i2 = 0; i2 < 4; i2++)
                    #pragma unroll
                    for (int j2 = 0; j2 < 4; j2++)
                        acc += s->xs[i2 * 16 + j2 * 4 + idx][c];
                s->Sk[idx][c] = acc;
            }
        }
        __syncthreads();

        // Phase B: 112 matmul rows x 4 quarters, 8 FFMA chains per thread.
        if (tid < 448) {
            const float* Wl = rootRow ? &s->R[l][0][0] : (&s->W[l][0][0][0] + wOff);
            float acc[8];
            #pragma unroll
            for (int q = 0; q < 8; q++) acc[q] = 0.0f;
            #pragma unroll 8
            for (int k = 0; k < 32; k++) {
                float a = (opA[k] - opB[k]) * scale;
                const float4* w4 = reinterpret_cast<const float4*>(Wl + k * 32 + cc);
                float4 w0 = w4[0], w1 = w4[1];
                acc[0] += a * w0.x; acc[1] += a * w0.y;
                acc[2] += a * w0.z; acc[3] += a * w0.w;
                acc[4] += a * w1.x; acc[5] += a * w1.y;
                acc[6] += a * w1.z; acc[7] += a * w1.w;
            }
            float4* d4 = reinterpret_cast<float4*>(dst);
            d4[0] = make_float4(acc[0], acc[1], acc[2], acc[3]);
            d4[1] = make_float4(acc[4], acc[5], acc[6], acc[7]);
        }
        __syncthreads();

        // Phase C: combine + ReLU + LayerNorm (64 nodes x 8 groups of 4 ch).
        {
            const float4 vb = *reinterpret_cast<const float4*>(&s->bias[l][ch0]);
            const float4 v0 = *reinterpret_cast<const float4*>(&s->AW[0][rij][ch0]);
            const float4 v1 = *reinterpret_cast<const float4*>(&s->AW[1][rij][ch0]);
            const float4 v2 = *reinterpret_cast<const float4*>(&s->AW[2][rik][ch0]);
            const float4 vr = *reinterpret_cast<const float4*>(&s->Hroot[nd][ch0]);
            float h[4];
            h[0] = vb.x + v0.x + v1.x + v2.x + vr.x;
            h[1] = vb.y + v0.y + v1.y + v2.y + vr.y;
            h[2] = vb.z + v0.z + v1.z + v2.z + vr.z;
            h[3] = vb.w + v0.w + v1.w + v2.w + vr.w;
            float ssum = 0.0f;
            #pragma unroll
            for (int q = 0; q < 4; q++) { h[q] = fmaxf(h[q], 0.0f); ssum += h[q]; }
            ssum += __shfl_xor_sync(0xffffffffu, ssum, 1);
            ssum += __shfl_xor_sync(0xffffffffu, ssum, 2);
            ssum += __shfl_xor_sync(0xffffffffu, ssum, 4);
            float mu = ssum * (1.0f / 32.0f);
            float vsum = 0.0f;
            #pragma unroll
            for (int q = 0; q < 4; q++) { float d = h[q] - mu; h[q] = d; vsum += d * d; }
            vsum += __shfl_xor_sync(0xffffffffu, vsum, 1);
            vsum += __shfl_xor_sync(0xffffffffu, vsum, 2);
            vsum += __shfl_xor_sync(0xffffffffu, vsum, 4);
            float rs = rsqrtf(vsum * (1.0f / 32.0f) + LN_EPS);
            #pragma unroll
            for (int q = 0; q < 4; q++) {
                int c = ch0 + q;
                s->xs[nd][c] = h[q] * rs * s->lng[c] + s->lnb[c];
            }
        }
        __syncthreads();
    }

    // ---- output: three axis-means over the 4x4x4 frame -> (48, 32) ----
    float* outb = out + (size_t)b * 48 * 32;
    #pragma unroll
    for (int v = tid; v < 1536; v += TPB) {
        int o = v >> 5, c = v & 31;
        float val;
        if (o < 16) {               // mean over i; o = j*4+k
            val = s->xs[o][c] + s->xs[o + 16][c] + s->xs[o + 32][c] + s->xs[o + 48][c];
        } else if (o < 32) {        // mean over j; (o-16) = i*4+k
            int oo = o - 16; int base = (oo >> 2) * 16 + (oo & 3);
            val = s->xs[base][c] + s->xs[base + 4][c] + s->xs[base + 8][c] + s->xs[base + 12][c];
        } else {                    // mean over k; (o-32) = i*4+j
            int oo = o - 32; int base = (oo >> 2) * 16 + (oo & 3) * 4;
            val = s->xs[base][c] + s->xs[base + 1][c] + s->xs[base + 2][c] + s->xs[base + 3][c];
        }
        outb[o * 32 + c] = val * 0.25f;
    }
}

extern "C" void kernel_launch(void* const* d_in, const int* in_sizes, int n_in,
                              void* d_out, int out_size) {
    const float* xx        = (const float*)d_in[0];
    const float* ss        = (const float*)d_in[1];
    const float* W_f       = (const float*)d_in[2];
    const float* b_f       = (const float*)d_in[3];
    const float* conv_w    = (const float*)d_in[4];
    const float* conv_root = (const float*)d_in[5];
    const float* conv_bias = (const float*)d_in[6];
    const float* ln_g      = (const float*)d_in[7];
    const float* ln_b      = (const float*)d_in[8];
    // d_in[9]/d_in[10] (src/dst) unused: aggregation has a closed form.

    const int B = in_sizes[1];

    cudaFuncSetAttribute(gnn_frame0_kernel,
                         cudaFuncAttributeMaxDynamicSharedMemorySize,
                         (int)sizeof(Smem));
    gnn_frame0_kernel<<<B, TPB, sizeof(Smem)>>>(
        xx, ss, W_f, b_f, conv_w, conv_root, conv_bias, ln_g, ln_b,
        (float*)d_out);
}

// round 5
// speedup vs baseline: 1.3725x; 1.3725x over previous
#include <cuda_runtime.h>

#define TPB 256
#define NLAYER 4
#define LN_EPS 1e-5f

typedef unsigned long long u64;

// Packed fp32-pair ops (Blackwell f32x2 pipe; ptxas never auto-fuses these).
__device__ __forceinline__ void fma2(u64& acc, u64 a, u64 w) {
    asm("fma.rn.f32x2 %0, %1, %2, %0;" : "+l"(acc) : "l"(a), "l"(w));
}
__device__ __forceinline__ u64 pack2(float v) {
    u64 r; asm("mov.b64 %0, {%1, %1};" : "=l"(r) : "f"(v)); return r;
}
__device__ __forceinline__ void mul2(u64& a, u64 b) {
    asm("mul.rn.f32x2 %0, %0, %1;" : "+l"(a) : "l"(b));
}

// ~95.4 KB shared per block -> 2 blocks/SM (grid=256 over 148 SMs).
struct __align__(16) Smem {
    float R[NLAYER][32][32];        // conv_root
    float W[NLAYER][3][32][32];     // conv_w
    float bias[NLAYER][32];         // conv_bias
    float Wf[6][32];                // W_f
    float bf[32];
    float lng[32];
    float lnb[32];
    float xs[64][33];               // node features, stride 33
    float Lij[16][33];              // line sums over k, rows (i*4+j)
    float Lik[16][33];              // line sums over j, rows (i*4+k)
    float Si[4][33];                // plane sums over (j,k)
    float Sj[4][33];                // plane sums over (i,k)
    float Sk[4][33];                // plane sums over (i,j)
    float AW[3][16][36];            // agg_r @ W_r   (stride 36 -> 16B ok)
    float Hroot[64][36];            // x @ R         (stride 36 -> 16B ok)
    float zero[36];                 // uniform zero operand for root rows
};

__global__ __launch_bounds__(TPB) void gnn_frame0_kernel(
    const float* __restrict__ xx, const float* __restrict__ ss,
    const float* __restrict__ W_f, const float* __restrict__ b_f,
    const float* __restrict__ conv_w, const float* __restrict__ conv_root,
    const float* __restrict__ conv_bias, const float* __restrict__ ln_g,
    const float* __restrict__ ln_b, float* __restrict__ out)
{
    extern __shared__ __align__(16) unsigned char smem_raw[];
    Smem* s = reinterpret_cast<Smem*>(smem_raw);
    const int tid = threadIdx.x;
    const int b = blockIdx.x;

    // ---- stage weights (float4, coalesced) ----
    {
        float4*       dRW = reinterpret_cast<float4*>(&s->R[0][0][0]);
        const float4* gR  = reinterpret_cast<const float4*>(conv_root);
        const float4* gW  = reinterpret_cast<const float4*>(conv_w);
        #pragma unroll
        for (int i = tid; i < 4096; i += TPB)
            dRW[i] = (i < 1024) ? gR[i] : gW[i - 1024];
        if (tid < 32) {
            reinterpret_cast<float4*>(&s->bias[0][0])[tid] =
                reinterpret_cast<const float4*>(conv_bias)[tid];
        } else if (tid < 80) {
            reinterpret_cast<float4*>(&s->Wf[0][0])[tid - 32] =
                reinterpret_cast<const float4*>(W_f)[tid - 32];
        } else if (tid < 112) {
            s->bf[tid - 80] = b_f[tid - 80];
        } else if (tid < 144) {
            s->lng[tid - 112] = ln_g[tid - 112];
        } else if (tid < 176) {
            s->lnb[tid - 144] = ln_b[tid - 144];
        } else if (tid < 212) {
            s->zero[tid - 176] = 0.0f;
        }
    }

    // thread -> (node, 8-channel group) for init / combine phases
    const int nd  = tid >> 2;
    const int ch0 = (tid & 3) * 8;
    const int ii = nd >> 4, jj = (nd >> 2) & 3, kk = nd & 3;
    const int rij = (ii << 2) | jj;
    const int rik = (ii << 2) | kk;

    __syncthreads();

    // ---- initial features (frame t=0): x0 = feats @ W_f + b_f ----
    {
        const float fi = ii * (1.0f / 3.0f);
        const float fj = jj * (1.0f / 3.0f);
        const float fk = kk * (1.0f / 3.0f);
        const float v  = xx[b * 512 + nd];   // frame 0 = first 64 nodes
        const float m  = ss[b] * 0.125f;     // ss / T
        #pragma unroll
        for (int q = 0; q < 8; q++) {
            int c = ch0 + q;
            s->xs[nd][c] = s->bf[c] + fi * s->Wf[0][c] + fj * s->Wf[1][c]
                         + fk * s->Wf[2][c] + v * s->Wf[4][c] + m * s->Wf[5][c];
        }
    }
    __syncthreads();

    // ---- matmul-phase mapping (224 active): 112 rows x 2 half-groups ----
    const int row  = tid >> 1;
    const int cc   = (tid & 1) * 16;
    const float* opA = s->zero;
    const float* opB = s->zero;
    float* dst = s->zero;              // inactive threads never store
    float scale = 0.0f;
    int  wOff = 0;
    bool rootRow = false;
    if (tid < 224) {
        if (row < 48) {
            int r = row >> 4, sr = row & 15;
            wOff = r * 1024;
            dst  = &s->AW[r][sr][cc];
            opB  = (r == 2) ? s->Lik[sr] : s->Lij[sr];
            opA  = (r == 0) ? s->Si[sr >> 2] : (r == 1 ? s->Sj[sr & 3] : s->Sk[sr & 3]);
            scale = 1.0f / 12.0f;
        } else {
            int n2 = row - 48;
            dst  = &s->Hroot[n2][cc];
            opA  = s->xs[n2];
            scale = 1.0f;
            rootRow = true;
        }
    }

    // ---- 4 R-GCN layers ----
    for (int l = 0; l < NLAYER; l++) {
        // Phase A: line sums (512 items) + plane sums (384 items), one sync.
        #pragma unroll
        for (int v = tid; v < 512; v += TPB) {
            int rr = v >> 5, c = v & 31;
            s->Lij[rr][c] = s->xs[rr * 4 + 0][c] + s->xs[rr * 4 + 1][c]
                          + s->xs[rr * 4 + 2][c] + s->xs[rr * 4 + 3][c];
            int base = (rr >> 2) * 16 + (rr & 3);
            s->Lik[rr][c] = s->xs[base][c] + s->xs[base + 4][c]
                          + s->xs[base + 8][c] + s->xs[base + 12][c];
        }
        #pragma unroll
        for (int t = tid; t < 384; t += TPB) {
            int which = t >> 7, idx = (t >> 5) & 3, c = t & 31;
            float acc = 0.0f;
            if (which == 0) {          // Si[i] = sum over (j,k)
                #pragma unroll
                for (int m = 0; m < 16; m++) acc += s->xs[idx * 16 + m][c];
                s->Si[idx][c] = acc;
            } else if (which == 1) {   // Sj[j] = sum over (i,k)
                #pragma unroll
                for (int i2 = 0; i2 < 4; i2++)
                    #pragma unroll
                    for (int k2 = 0; k2 < 4; k2++)
                        acc += s->xs[i2 * 16 + idx * 4 + k2][c];
                s->Sj[idx][c] = acc;
            } else {                   // Sk[k] = sum over (i,j)
                #pragma unroll
                for (int i2 = 0; i2 < 4; i2++)
                    #pragma unroll
                    for (int j2 = 0; j2 < 4; j2++)
                        acc += s->xs[i2 * 16 + j2 * 4 + idx][c];
                s->Sk[idx][c] = acc;
            }
        }
        __syncthreads();

        // Phase B: 112 rows x 2 halves; 8 packed f32x2 FMA chains per thread.
        if (tid < 224) {
            const float* Wl = rootRow ? &s->R[l][0][0] : (&s->W[l][0][0][0] + wOff);
            u64 acc[8];
            #pragma unroll
            for (int q = 0; q < 8; q++) acc[q] = 0ull;
            #pragma unroll 8
            for (int k = 0; k < 32; k++) {
                u64 a2 = pack2(opA[k] - opB[k]);       // scale folded out
                const ulonglong2* w2 = reinterpret_cast<const ulonglong2*>(Wl + k * 32 + cc);
                ulonglong2 wa = w2[0], wb = w2[1], wc = w2[2], wd = w2[3];
                fma2(acc[0], a2, wa.x); fma2(acc[1], a2, wa.y);
                fma2(acc[2], a2, wb.x); fma2(acc[3], a2, wb.y);
                fma2(acc[4], a2, wc.x); fma2(acc[5], a2, wc.y);
                fma2(acc[6], a2, wd.x); fma2(acc[7], a2, wd.y);
            }
            u64 s2 = pack2(scale);
            #pragma unroll
            for (int q = 0; q < 8; q++) mul2(acc[q], s2);
            ulonglong2* d2 = reinterpret_cast<ulonglong2*>(dst);
            d2[0] = make_ulonglong2(acc[0], acc[1]);
            d2[1] = make_ulonglong2(acc[2], acc[3]);
            d2[2] = make_ulonglong2(acc[4], acc[5]);
            d2[3] = make_ulonglong2(acc[6], acc[7]);
        }
        __syncthreads();

        // Phase C: combine + ReLU + LayerNorm (64 nodes x 4 groups of 8 ch).
        {
            float h[8];
            const float4* b4 = reinterpret_cast<const float4*>(&s->bias[l][ch0]);
            const float4* a0 = reinterpret_cast<const float4*>(&s->AW[0][rij][ch0]);
            const float4* a1 = reinterpret_cast<const float4*>(&s->AW[1][rij][ch0]);
            const float4* a2 = reinterpret_cast<const float4*>(&s->AW[2][rik][ch0]);
            const float4* hr = reinterpret_cast<const float4*>(&s->Hroot[nd][ch0]);
            #pragma unroll
            for (int q4 = 0; q4 < 2; q4++) {
                float4 vb = b4[q4], v0 = a0[q4], v1 = a1[q4], v2 = a2[q4], vr = hr[q4];
                h[q4 * 4 + 0] = vb.x + v0.x + v1.x + v2.x + vr.x;
                h[q4 * 4 + 1] = vb.y + v0.y + v1.y + v2.y + vr.y;
                h[q4 * 4 + 2] = vb.z + v0.z + v1.z + v2.z + vr.z;
                h[q4 * 4 + 3] = vb.w + v0.w + v1.w + v2.w + vr.w;
            }
            float ssum = 0.0f;
            #pragma unroll
            for (int q = 0; q < 8; q++) { h[q] = fmaxf(h[q], 0.0f); ssum += h[q]; }
            ssum += __shfl_xor_sync(0xffffffffu, ssum, 1);
            ssum += __shfl_xor_sync(0xffffffffu, ssum, 2);
            float mu = ssum * (1.0f / 32.0f);
            float vsum = 0.0f;
            #pragma unroll
            for (int q = 0; q < 8; q++) { float d = h[q] - mu; h[q] = d; vsum += d * d; }
            vsum += __shfl_xor_sync(0xffffffffu, vsum, 1);
            vsum += __shfl_xor_sync(0xffffffffu, vsum, 2);
            float rs = rsqrtf(vsum * (1.0f / 32.0f) + LN_EPS);
            #pragma unroll
            for (int q = 0; q < 8; q++) {
                int c = ch0 + q;
                s->xs[nd][c] = h[q] * rs * s->lng[c] + s->lnb[c];
            }
        }
        __syncthreads();
    }

    // ---- output: three axis-means over the 4x4x4 frame -> (48, 32) ----
    float* outb = out + (size_t)b * 48 * 32;
    #pragma unroll
    for (int v = tid; v < 1536; v += TPB) {
        int o = v >> 5, c = v & 31;
        float val;
        if (o < 16) {               // mean over i; o = j*4+k
            val = s->xs[o][c] + s->xs[o + 16][c] + s->xs[o + 32][c] + s->xs[o + 48][c];
        } else if (o < 32) {        // mean over j; (o-16) = i*4+k
            int oo = o - 16; int base = (oo >> 2) * 16 + (oo & 3);
            val = s->xs[base][c] + s->xs[base + 4][c] + s->xs[base + 8][c] + s->xs[base + 12][c];
        } else {                    // mean over k; (o-32) = i*4+j
            int oo = o - 32; int base = (oo >> 2) * 16 + (oo & 3) * 4;
            val = s->xs[base][c] + s->xs[base + 1][c] + s->xs[base + 2][c] + s->xs[base + 3][c];
        }
        outb[o * 32 + c] = val * 0.25f;
    }
}

extern "C" void kernel_launch(void* const* d_in, const int* in_sizes, int n_in,
                              void* d_out, int out_size) {
    const float* xx        = (const float*)d_in[0];
    const float* ss        = (const float*)d_in[1];
    const float* W_f       = (const float*)d_in[2];
    const float* b_f       = (const float*)d_in[3];
    const float* conv_w    = (const float*)d_in[4];
    const float* conv_root = (const float*)d_in[5];
    const float* conv_bias = (const float*)d_in[6];
    const float* ln_g      = (const float*)d_in[7];
    const float* ln_b      = (const float*)d_in[8];
    // d_in[9]/d_in[10] (src/dst) unused: aggregation has a closed form.

    const int B = in_sizes[1];

    cudaFuncSetAttribute(gnn_frame0_kernel,
                         cudaFuncAttributeMaxDynamicSharedMemorySize,
                         (int)sizeof(Smem));
    gnn_frame0_kernel<<<B, TPB, sizeof(Smem)>>>(
        xx, ss, W_f, b_f, conv_w, conv_root, conv_bias, ln_g, ln_b,
        (float*)d_out);
}

// round 6
// speedup vs baseline: 1.4043x; 1.0232x over previous
#include <cuda_runtime.h>

#define TPB 256
#define NLAYER 4
#define LN_EPS 1e-5f

typedef unsigned long long u64;

// Packed fp32-pair ops (Blackwell f32x2 pipe; ptxas never auto-fuses these).
__device__ __forceinline__ void fma2(u64& acc, u64 a, u64 w) {
    asm("fma.rn.f32x2 %0, %1, %2, %0;" : "+l"(acc) : "l"(a), "l"(w));
}
__device__ __forceinline__ u64 pack2(float v) {
    u64 r; asm("mov.b64 %0, {%1, %1};" : "=l"(r) : "f"(v)); return r;
}
__device__ __forceinline__ void mul2(u64& a, u64 b) {
    asm("mul.rn.f32x2 %0, %0, %1;" : "+l"(a) : "l"(b));
}
__device__ __forceinline__ void add2(u64& a, u64 b) {
    asm("add.rn.f32x2 %0, %0, %1;" : "+l"(a) : "l"(b));
}

// ~95.4 KB shared per block -> 2 blocks/SM (grid=256 over 148 SMs).
struct __align__(16) Smem {
    float R[NLAYER][32][32];        // conv_root
    float W[NLAYER][3][32][32];     // conv_w
    float bias[NLAYER][32];         // conv_bias
    float Wf[6][32];                // W_f
    float bf[32];
    float lng[32];
    float lnb[32];
    float xs[64][33];               // node features, stride 33
    float Lij[16][33];              // line sums over k, rows (i*4+j)
    float Lik[16][33];              // line sums over j, rows (i*4+k)
    float Si[4][33];                // plane sums over (j,k)
    float Sj[4][33];                // plane sums over (i,k)
    float Sk[4][33];                // plane sums over (i,j)
    float AW[3][16][36];            // agg_r @ W_r   (stride 36 -> 16B ok)
    float Hroot[64][36];            // x @ R + bias  (stride 36 -> 16B ok)
    float zero[36];                 // guard operand for inactive threads
};

__global__ __launch_bounds__(TPB) void gnn_frame0_kernel(
    const float* __restrict__ xx, const float* __restrict__ ss,
    const float* __restrict__ W_f, const float* __restrict__ b_f,
    const float* __restrict__ conv_w, const float* __restrict__ conv_root,
    const float* __restrict__ conv_bias, const float* __restrict__ ln_g,
    const float* __restrict__ ln_b, float* __restrict__ out)
{
    extern __shared__ __align__(16) unsigned char smem_raw[];
    Smem* s = reinterpret_cast<Smem*>(smem_raw);
    const int tid = threadIdx.x;
    const int b = blockIdx.x;

    // ---- stage weights (float4, coalesced) ----
    {
        float4*       dRW = reinterpret_cast<float4*>(&s->R[0][0][0]);
        const float4* gR  = reinterpret_cast<const float4*>(conv_root);
        const float4* gW  = reinterpret_cast<const float4*>(conv_w);
        #pragma unroll
        for (int i = tid; i < 4096; i += TPB)
            dRW[i] = (i < 1024) ? gR[i] : gW[i - 1024];
        if (tid < 32) {
            reinterpret_cast<float4*>(&s->bias[0][0])[tid] =
                reinterpret_cast<const float4*>(conv_bias)[tid];
        } else if (tid < 80) {
            reinterpret_cast<float4*>(&s->Wf[0][0])[tid - 32] =
                reinterpret_cast<const float4*>(W_f)[tid - 32];
        } else if (tid < 112) {
            s->bf[tid - 80] = b_f[tid - 80];
        } else if (tid < 144) {
            s->lng[tid - 112] = ln_g[tid - 112];
        } else if (tid < 176) {
            s->lnb[tid - 144] = ln_b[tid - 144];
        } else if (tid < 212) {
            s->zero[tid - 176] = 0.0f;
        }
    }

    // thread -> (node, 8-channel group) for init / combine phases
    const int nd  = tid >> 2;
    const int ch0 = (tid & 3) * 8;
    const int ii = nd >> 4, jj = (nd >> 2) & 3, kk = nd & 3;
    const int rij = (ii << 2) | jj;
    const int rik = (ii << 2) | kk;

    __syncthreads();

    // ---- initial features (frame t=0): x0 = feats @ W_f + b_f ----
    {
        const float fi = ii * (1.0f / 3.0f);
        const float fj = jj * (1.0f / 3.0f);
        const float fk = kk * (1.0f / 3.0f);
        const float v  = xx[b * 512 + nd];   // frame 0 = first 64 nodes
        const float m  = ss[b] * 0.125f;     // ss / T
        #pragma unroll
        for (int q = 0; q < 8; q++) {
            int c = ch0 + q;
            s->xs[nd][c] = s->bf[c] + fi * s->Wf[0][c] + fj * s->Wf[1][c]
                         + fk * s->Wf[2][c] + v * s->Wf[4][c] + m * s->Wf[5][c];
        }
    }
    __syncthreads();

    // ---- matmul-phase mapping (224 active): 112 rows x 2 half-groups ----
    // rows 0..47  -> AW (warps 0..2), rows 48..111 -> root (warps 3..6)
    const int row  = tid >> 1;
    const int cc   = (tid & 1) * 16;
    const float* opA = s->zero;
    const float* opB = s->zero;
    const float* xrow = s->zero;
    float* dst = s->zero;              // inactive threads never store
    int  wOff = 0;
    if (tid < 224) {
        if (row < 48) {
            int r = row >> 4, sr = row & 15;
            wOff = r * 1024;
            dst  = &s->AW[r][sr][cc];
            opB  = (r == 2) ? s->Lik[sr] : s->Lij[sr];
            opA  = (r == 0) ? s->Si[sr >> 2] : (r == 1 ? s->Sj[sr & 3] : s->Sk[sr & 3]);
        } else {
            int n2 = row - 48;
            dst  = &s->Hroot[n2][cc];
            xrow = s->xs[n2];
        }
    }

    // ---- 4 R-GCN layers ----
    for (int l = 0; l < NLAYER; l++) {
        // Phase A: line sums (512 items) + plane sums (384 items), one sync.
        #pragma unroll
        for (int v = tid; v < 512; v += TPB) {
            int rr = v >> 5, c = v & 31;
            s->Lij[rr][c] = s->xs[rr * 4 + 0][c] + s->xs[rr * 4 + 1][c]
                          + s->xs[rr * 4 + 2][c] + s->xs[rr * 4 + 3][c];
            int base = (rr >> 2) * 16 + (rr & 3);
            s->Lik[rr][c] = s->xs[base][c] + s->xs[base + 4][c]
                          + s->xs[base + 8][c] + s->xs[base + 12][c];
        }
        #pragma unroll
        for (int t = tid; t < 384; t += TPB) {
            int which = t >> 7, idx = (t >> 5) & 3, c = t & 31;
            float acc = 0.0f;
            if (which == 0) {          // Si[i] = sum over (j,k)
                #pragma unroll
                for (int m = 0; m < 16; m++) acc += s->xs[idx * 16 + m][c];
                s->Si[idx][c] = acc;
            } else if (which == 1) {   // Sj[j] = sum over (i,k)
                #pragma unroll
                for (int i2 = 0; i2 < 4; i2++)
                    #pragma unroll
                    for (int k2 = 0; k2 < 4; k2++)
                        acc += s->xs[i2 * 16 + idx * 4 + k2][c];
                s->Sj[idx][c] = acc;
            } else {                   // Sk[k] = sum over (i,j)
                #pragma unroll
                for (int i2 = 0; i2 < 4; i2++)
                    #pragma unroll
                    for (int j2 = 0; j2 < 4; j2++)
                        acc += s->xs[i2 * 16 + j2 * 4 + idx][c];
                s->Sk[idx][c] = acc;
            }
        }
        __syncthreads();

        // Phase B: 112 rows x 2 halves; warp-uniform AW vs root loops.
        if (tid < 224) {
            u64 acc[8];
            #pragma unroll
            for (int q = 0; q < 8; q++) acc[q] = 0ull;
            if (row < 48) {
                // AW rows: a = plane - line (scale 1/12 applied at the end)
                const float* Wl = &s->W[l][0][0][0] + wOff;
                #pragma unroll 8
                for (int k = 0; k < 32; k++) {
                    u64 a2 = pack2(opA[k] - opB[k]);
                    const ulonglong2* w2 = reinterpret_cast<const ulonglong2*>(Wl + k * 32 + cc);
                    ulonglong2 wa = w2[0], wb = w2[1], wc = w2[2], wd = w2[3];
                    fma2(acc[0], a2, wa.x); fma2(acc[1], a2, wa.y);
                    fma2(acc[2], a2, wb.x); fma2(acc[3], a2, wb.y);
                    fma2(acc[4], a2, wc.x); fma2(acc[5], a2, wc.y);
                    fma2(acc[6], a2, wd.x); fma2(acc[7], a2, wd.y);
                }
                u64 s2 = pack2(1.0f / 12.0f);
                #pragma unroll
                for (int q = 0; q < 8; q++) mul2(acc[q], s2);
            } else {
                // root rows: a = x directly; bias folded in at the end
                const float* Wl = &s->R[l][0][0];
                #pragma unroll 8
                for (int k = 0; k < 32; k++) {
                    u64 a2 = pack2(xrow[k]);
                    const ulonglong2* w2 = reinterpret_cast<const ulonglong2*>(Wl + k * 32 + cc);
                    ulonglong2 wa = w2[0], wb = w2[1], wc = w2[2], wd = w2[3];
                    fma2(acc[0], a2, wa.x); fma2(acc[1], a2, wa.y);
                    fma2(acc[2], a2, wb.x); fma2(acc[3], a2, wb.y);
                    fma2(acc[4], a2, wc.x); fma2(acc[5], a2, wc.y);
                    fma2(acc[6], a2, wd.x); fma2(acc[7], a2, wd.y);
                }
                const ulonglong2* bb = reinterpret_cast<const ulonglong2*>(&s->bias[l][cc]);
                ulonglong2 b0 = bb[0], b1 = bb[1];
                add2(acc[0], b0.x); add2(acc[1], b0.y);
                add2(acc[2], b1.x); add2(acc[3], b1.y);
                const ulonglong2* bb2 = reinterpret_cast<const ulonglong2*>(&s->bias[l][cc + 8]);
                ulonglong2 b2 = bb2[0], b3 = bb2[1];
                add2(acc[4], b2.x); add2(acc[5], b2.y);
                add2(acc[6], b3.x); add2(acc[7], b3.y);
            }
            ulonglong2* d2 = reinterpret_cast<ulonglong2*>(dst);
            d2[0] = make_ulonglong2(acc[0], acc[1]);
            d2[1] = make_ulonglong2(acc[2], acc[3]);
            d2[2] = make_ulonglong2(acc[4], acc[5]);
            d2[3] = make_ulonglong2(acc[6], acc[7]);
        }
        __syncthreads();

        // Phase C: combine + ReLU + LayerNorm (64 nodes x 4 groups of 8 ch).
        {
            float h[8];
            const float4* a0 = reinterpret_cast<const float4*>(&s->AW[0][rij][ch0]);
            const float4* a1 = reinterpret_cast<const float4*>(&s->AW[1][rij][ch0]);
            const float4* a2 = reinterpret_cast<const float4*>(&s->AW[2][rik][ch0]);
            const float4* hr = reinterpret_cast<const float4*>(&s->Hroot[nd][ch0]);
            #pragma unroll
            for (int q4 = 0; q4 < 2; q4++) {
                float4 v0 = a0[q4], v1 = a1[q4], v2 = a2[q4], vr = hr[q4];
                h[q4 * 4 + 0] = v0.x + v1.x + v2.x + vr.x;
                h[q4 * 4 + 1] = v0.y + v1.y + v2.y + vr.y;
                h[q4 * 4 + 2] = v0.z + v1.z + v2.z + vr.z;
                h[q4 * 4 + 3] = v0.w + v1.w + v2.w + vr.w;
            }
            // parallel sum / sum-of-squares reductions (var = E[x^2] - mu^2)
            float ssum = 0.0f, sq = 0.0f;
            #pragma unroll
            for (int q = 0; q < 8; q++) {
                h[q] = fmaxf(h[q], 0.0f);
                ssum += h[q];
                sq   += h[q] * h[q];
            }
            ssum += __shfl_xor_sync(0xffffffffu, ssum, 1);
            sq   += __shfl_xor_sync(0xffffffffu, sq, 1);
            ssum += __shfl_xor_sync(0xffffffffu, ssum, 2);
            sq   += __shfl_xor_sync(0xffffffffu, sq, 2);
            float mu  = ssum * (1.0f / 32.0f);
            float var = sq * (1.0f / 32.0f) - mu * mu;
            float rs  = rsqrtf(var + LN_EPS);
            #pragma unroll
            for (int q = 0; q < 8; q++) {
                int c = ch0 + q;
                s->xs[nd][c] = (h[q] - mu) * rs * s->lng[c] + s->lnb[c];
            }
        }
        __syncthreads();
    }

    // ---- output: three axis-means over the 4x4x4 frame -> (48, 32) ----
    float* outb = out + (size_t)b * 48 * 32;
    #pragma unroll
    for (int v = tid; v < 1536; v += TPB) {
        int o = v >> 5, c = v & 31;
        float val;
        if (o < 16) {               // mean over i; o = j*4+k
            val = s->xs[o][c] + s->xs[o + 16][c] + s->xs[o + 32][c] + s->xs[o + 48][c];
        } else if (o < 32) {        // mean over j; (o-16) = i*4+k
            int oo = o - 16; int base = (oo >> 2) * 16 + (oo & 3);
            val = s->xs[base][c] + s->xs[base + 4][c] + s->xs[base + 8][c] + s->xs[base + 12][c];
        } else {                    // mean over k; (o-32) = i*4+j
            int oo = o - 32; int base = (oo >> 2) * 16 + (oo & 3) * 4;
            val = s->xs[base][c] + s->xs[base + 1][c] + s->xs[base + 2][c] + s->xs[base + 3][c];
        }
        outb[o * 32 + c] = val * 0.25f;
    }
}

extern "C" void kernel_launch(void* const* d_in, const int* in_sizes, int n_in,
                              void* d_out, int out_size) {
    const float* xx        = (const float*)d_in[0];
    const float* ss        = (const float*)d_in[1];
    const float* W_f       = (const float*)d_in[2];
    const float* b_f       = (const float*)d_in[3];
    const float* conv_w    = (const float*)d_in[4];
    const float* conv_root = (const float*)d_in[5];
    const float* conv_bias = (const float*)d_in[6];
    const float* ln_g      = (const float*)d_in[7];
    const float* ln_b      = (const float*)d_in[8];
    // d_in[9]/d_in[10] (src/dst) unused: aggregation has a closed form.

    const int B = in_sizes[1];

    cudaFuncSetAttribute(gnn_frame0_kernel,
                         cudaFuncAttributeMaxDynamicSharedMemorySize,
                         (int)sizeof(Smem));
    gnn_frame0_kernel<<<B, TPB, sizeof(Smem)>>>(
        xx, ss, W_f, b_f, conv_w, conv_root, conv_bias, ln_g, ln_b,
        (float*)d_out);
}

// round 9
// speedup vs baseline: 1.4726x; 1.0486x over previous
#include <cuda_runtime.h>

#define TPB 256
#define NLAYER 4
#define LN_EPS 1e-5f

typedef unsigned long long u64;

// Packed fp32-pair ops (Blackwell f32x2 pipe; ptxas never auto-fuses these).
__device__ __forceinline__ void fma2(u64& acc, u64 a, u64 w) {
    asm("fma.rn.f32x2 %0, %1, %2, %0;" : "+l"(acc) : "l"(a), "l"(w));
}
__device__ __forceinline__ u64 pack2(float v) {
    u64 r; asm("mov.b64 %0, {%1, %1};" : "=l"(r) : "f"(v)); return r;
}
__device__ __forceinline__ void mul2(u64& a, u64 b) {
    asm("mul.rn.f32x2 %0, %0, %1;" : "+l"(a) : "l"(b));
}
__device__ __forceinline__ void add2(u64& a, u64 b) {
    asm("add.rn.f32x2 %0, %0, %1;" : "+l"(a) : "l"(b));
}

// ~99 KB shared -> 2 blocks/SM. All hot arrays stride-36 rows (16B aligned).
struct __align__(16) Smem {
    float R[NLAYER][32][32];        // conv_root
    float W[NLAYER][3][32][32];     // conv_w
    float bias[NLAYER][32];
    float Wf[6][32];
    float bf[32], lng[32], lnb[32];
    float xs[64][36];               // node features
    float Lij[16][36];              // line sums over k, rows (i*4+j)
    float Lik[16][36];              // line sums over j, rows (i*4+k)
    float Si[4][36];                // plane sums over (j,k)
    float Sj[4][36];                // plane sums over (i,k)
    float Sk[4][36];                // plane sums over (i,j)
    float AW[3][16][36];            // agg_r @ W_r
    float Hroot[64][36];            // x @ R + bias
    float zero[36];                 // guard operand for inactive threads
};

__global__ __launch_bounds__(TPB) void gnn_frame0_kernel(
    const float* __restrict__ xx, const float* __restrict__ ss,
    const float* __restrict__ W_f, const float* __restrict__ b_f,
    const float* __restrict__ conv_w, const float* __restrict__ conv_root,
    const float* __restrict__ conv_bias, const float* __restrict__ ln_g,
    const float* __restrict__ ln_b, float* __restrict__ out)
{
    extern __shared__ __align__(16) unsigned char smem_raw[];
    Smem* s = reinterpret_cast<Smem*>(smem_raw);
    const int tid = threadIdx.x;
    const int b = blockIdx.x;

    // ---- stage weights (float4, coalesced) ----
    {
        float4*       dRW = reinterpret_cast<float4*>(&s->R[0][0][0]);
        const float4* gR  = reinterpret_cast<const float4*>(conv_root);
        const float4* gW  = reinterpret_cast<const float4*>(conv_w);
        #pragma unroll
        for (int i = tid; i < 4096; i += TPB)
            dRW[i] = (i < 1024) ? gR[i] : gW[i - 1024];
        if (tid < 32) {
            reinterpret_cast<float4*>(&s->bias[0][0])[tid] =
                reinterpret_cast<const float4*>(conv_bias)[tid];
        } else if (tid < 80) {
            reinterpret_cast<float4*>(&s->Wf[0][0])[tid - 32] =
                reinterpret_cast<const float4*>(W_f)[tid - 32];
        } else if (tid < 112) {
            s->bf[tid - 80] = b_f[tid - 80];
        } else if (tid < 144) {
            s->lng[tid - 112] = ln_g[tid - 112];
        } else if (tid < 176) {
            s->lnb[tid - 144] = ln_b[tid - 144];
        } else if (tid < 212) {
            s->zero[tid - 176] = 0.0f;
        }
    }

    // thread -> (node, 8-channel group) for init / combine phases
    const int nd  = tid >> 2;
    const int ch0 = (tid & 3) * 8;
    const int ii = nd >> 4, jj = (nd >> 2) & 3, kk = nd & 3;
    const int rij = (ii << 2) | jj;
    const int rik = (ii << 2) | kk;

    __syncthreads();

    // ---- initial features (frame t=0): x0 = feats @ W_f + b_f ----
    {
        const float fi = ii * (1.0f / 3.0f);
        const float fj = jj * (1.0f / 3.0f);
        const float fk = kk * (1.0f / 3.0f);
        const float v  = xx[b * 512 + nd];   // frame 0 = first 64 nodes
        const float m  = ss[b] * 0.125f;     // ss / T
        #pragma unroll
        for (int q = 0; q < 8; q++) {
            int c = ch0 + q;
            s->xs[nd][c] = s->bf[c] + fi * s->Wf[0][c] + fj * s->Wf[1][c]
                         + fk * s->Wf[2][c] + v * s->Wf[4][c] + m * s->Wf[5][c];
        }
    }
    __syncthreads();

    // ---- Phase-B mapping: 56 row-pairs x 4 eighth-slices = 224 threads ----
    // pairs 0..23  -> AW (warps 0..2, one relation each; pair shares plane)
    // pairs 24..55 -> root (warps 3..6)
    const int pairIdx = tid >> 2;
    const int cc8 = (tid & 3) * 8;
    const float* aP  = s->zero;
    const float* aL0 = s->zero;
    const float* aL1 = s->zero;
    float* dst0 = s->zero;             // inactive threads never store
    float* dst1 = s->zero;
    int  wOff = 0;
    bool isRoot = false;
    if (tid < 224) {
        if (pairIdx < 24) {
            int r = pairIdx >> 3, t = pairIdx & 7;
            int rowA, rowB;
            wOff = r * 1024;
            if (r == 0) {            // rows i*4+j; pair same i (shares Si)
                rowA = 2 * t; rowB = 2 * t + 1;
                aP = s->Si[t >> 1]; aL0 = s->Lij[rowA]; aL1 = s->Lij[rowB];
            } else if (r == 1) {     // pair same j, i and i+1 (shares Sj)
                int j = t & 3, i0 = (t >> 2) * 2;
                rowA = i0 * 4 + j; rowB = (i0 + 1) * 4 + j;
                aP = s->Sj[j]; aL0 = s->Lij[rowA]; aL1 = s->Lij[rowB];
            } else {                 // pair same k, i and i+1 (shares Sk)
                int k = t & 3, i0 = (t >> 2) * 2;
                rowA = i0 * 4 + k; rowB = (i0 + 1) * 4 + k;
                aP = s->Sk[k]; aL0 = s->Lik[rowA]; aL1 = s->Lik[rowB];
            }
            dst0 = &s->AW[r][rowA][cc8];
            dst1 = &s->AW[r][rowB][cc8];
        } else {
            int n0 = (pairIdx - 24) * 2;
            aL0 = s->xs[n0]; aL1 = s->xs[n0 + 1];
            dst0 = &s->Hroot[n0][cc8];
            dst1 = &s->Hroot[n0 + 1][cc8];
            isRoot = true;
        }
    }

    // ---- 4 R-GCN layers ----
    for (int l = 0; l < NLAYER; l++) {
        // Phase A: line sums (512 items) + plane sums (384 items), one sync.
        #pragma unroll
        for (int v = tid; v < 512; v += TPB) {
            int rr = v >> 5, c = v & 31;
            s->Lij[rr][c] = s->xs[rr * 4 + 0][c] + s->xs[rr * 4 + 1][c]
                          + s->xs[rr * 4 + 2][c] + s->xs[rr * 4 + 3][c];
            int base = (rr >> 2) * 16 + (rr & 3);
            s->Lik[rr][c] = s->xs[base][c] + s->xs[base + 4][c]
                          + s->xs[base + 8][c] + s->xs[base + 12][c];
        }
        #pragma unroll
        for (int t = tid; t < 384; t += TPB) {
            int which = t >> 7, idx = (t >> 5) & 3, c = t & 31;
            float acc = 0.0f;
            if (which == 0) {
                #pragma unroll
                for (int m = 0; m < 16; m++) acc += s->xs[idx * 16 + m][c];
                s->Si[idx][c] = acc;
            } else if (which == 1) {
                #pragma unroll
                for (int i2 = 0; i2 < 4; i2++)
                    #pragma unroll
                    for (int k2 = 0; k2 < 4; k2++)
                        acc += s->xs[i2 * 16 + idx * 4 + k2][c];
                s->Sj[idx][c] = acc;
            } else {
                #pragma unroll
                for (int i2 = 0; i2 < 4; i2++)
                    #pragma unroll
                    for (int j2 = 0; j2 < 4; j2++)
                        acc += s->xs[i2 * 16 + j2 * 4 + idx][c];
                s->Sk[idx][c] = acc;
            }
        }
        __syncthreads();

        // Phase B: 2 rows x 8 channels per thread; weights loaded once per pair.
        if (tid < 224) {
            u64 acc0[4] = {0, 0, 0, 0}, acc1[4] = {0, 0, 0, 0};
            if (!isRoot) {
                const float* Wl = &s->W[l][0][0][0] + wOff;
                #pragma unroll
                for (int k0 = 0; k0 < 32; k0 += 4) {
                    float4 p4  = *reinterpret_cast<const float4*>(aP  + k0);
                    float4 l04 = *reinterpret_cast<const float4*>(aL0 + k0);
                    float4 l14 = *reinterpret_cast<const float4*>(aL1 + k0);
                    #pragma unroll
                    for (int kq = 0; kq < 4; kq++) {
                        float pv = (&p4.x)[kq];
                        u64 a0 = pack2(pv - (&l04.x)[kq]);
                        u64 a1 = pack2(pv - (&l14.x)[kq]);
                        const ulonglong2* w2 =
                            reinterpret_cast<const ulonglong2*>(Wl + (k0 + kq) * 32 + cc8);
                        ulonglong2 wA = w2[0], wB = w2[1];
                        fma2(acc0[0], a0, wA.x); fma2(acc0[1], a0, wA.y);
                        fma2(acc0[2], a0, wB.x); fma2(acc0[3], a0, wB.y);
                        fma2(acc1[0], a1, wA.x); fma2(acc1[1], a1, wA.y);
                        fma2(acc1[2], a1, wB.x); fma2(acc1[3], a1, wB.y);
                    }
                }
                u64 s2 = pack2(1.0f / 12.0f);
                #pragma unroll
                for (int q = 0; q < 4; q++) { mul2(acc0[q], s2); mul2(acc1[q], s2); }
            } else {
                const float* Wl = &s->R[l][0][0];
                #pragma unroll
                for (int k0 = 0; k0 < 32; k0 += 4) {
                    float4 l04 = *reinterpret_cast<const float4*>(aL0 + k0);
                    float4 l14 = *reinterpret_cast<const float4*>(aL1 + k0);
                    #pragma unroll
                    for (int kq = 0; kq < 4; kq++) {
                        u64 a0 = pack2((&l04.x)[kq]);
                        u64 a1 = pack2((&l14.x)[kq]);
                        const ulonglong2* w2 =
                            reinterpret_cast<const ulonglong2*>(Wl + (k0 + kq) * 32 + cc8);
                        ulonglong2 wA = w2[0], wB = w2[1];
                        fma2(acc0[0], a0, wA.x); fma2(acc0[1], a0, wA.y);
                        fma2(acc0[2], a0, wB.x); fma2(acc0[3], a0, wB.y);
                        fma2(acc1[0], a1, wA.x); fma2(acc1[1], a1, wA.y);
                        fma2(acc1[2], a1, wB.x); fma2(acc1[3], a1, wB.y);
                    }
                }
                const ulonglong2* bb =
                    reinterpret_cast<const ulonglong2*>(&s->bias[l][cc8]);
                ulonglong2 b0 = bb[0], b1 = bb[1];
                add2(acc0[0], b0.x); add2(acc0[1], b0.y);
                add2(acc0[2], b1.x); add2(acc0[3], b1.y);
                add2(acc1[0], b0.x); add2(acc1[1], b0.y);
                add2(acc1[2], b1.x); add2(acc1[3], b1.y);
            }
            ulonglong2* d0 = reinterpret_cast<ulonglong2*>(dst0);
            d0[0] = make_ulonglong2(acc0[0], acc0[1]);
            d0[1] = make_ulonglong2(acc0[2], acc0[3]);
            ulonglong2* d1 = reinterpret_cast<ulonglong2*>(dst1);
            d1[0] = make_ulonglong2(acc1[0], acc1[1]);
            d1[1] = make_ulonglong2(acc1[2], acc1[3]);
        }
        __syncthreads();

        // Phase C: combine + ReLU + LayerNorm (64 nodes x 4 groups of 8 ch).
        {
            float h[8];
            const float4* a0 = reinterpret_cast<const float4*>(&s->AW[0][rij][ch0]);
            const float4* a1 = reinterpret_cast<const float4*>(&s->AW[1][rij][ch0]);
            const float4* a2 = reinterpret_cast<const float4*>(&s->AW[2][rik][ch0]);
            const float4* hr = reinterpret_cast<const float4*>(&s->Hroot[nd][ch0]);
            #pragma unroll
            for (int q4 = 0; q4 < 2; q4++) {
                float4 v0 = a0[q4], v1 = a1[q4], v2 = a2[q4], vr = hr[q4];
                h[q4 * 4 + 0] = v0.x + v1.x + v2.x + vr.x;
                h[q4 * 4 + 1] = v0.y + v1.y + v2.y + vr.y;
                h[q4 * 4 + 2] = v0.z + v1.z + v2.z + vr.z;
                h[q4 * 4 + 3] = v0.w + v1.w + v2.w + vr.w;
            }
            float ssum = 0.0f, sq = 0.0f;
            #pragma unroll
            for (int q = 0; q < 8; q++) {
                h[q] = fmaxf(h[q], 0.0f);
                ssum += h[q];
                sq   += h[q] * h[q];
            }
            ssum += __shfl_xor_sync(0xffffffffu, ssum, 1);
            sq   += __shfl_xor_sync(0xffffffffu, sq, 1);
            ssum += __shfl_xor_sync(0xffffffffu, ssum, 2);
            sq   += __shfl_xor_sync(0xffffffffu, sq, 2);
            float mu  = ssum * (1.0f / 32.0f);
            float var = sq * (1.0f / 32.0f) - mu * mu;
            float rs  = rsqrtf(var + LN_EPS);
            #pragma unroll
            for (int q = 0; q < 8; q++) {
                int c = ch0 + q;
                s->xs[nd][c] = (h[q] - mu) * rs * s->lng[c] + s->lnb[c];
            }
        }
        __syncthreads();
    }

    // ---- output: three axis-means over the 4x4x4 frame -> (48, 32) ----
    float* outb = out + (size_t)b * 48 * 32;
    #pragma unroll
    for (int v = tid; v < 1536; v += TPB) {
        int o = v >> 5, c = v & 31;
        float val;
        if (o < 16) {               // mean over i; o = j*4+k
            val = s->xs[o][c] + s->xs[o + 16][c] + s->xs[o + 32][c] + s->xs[o + 48][c];
        } else if (o < 32) {        // mean over j; (o-16) = i*4+k
            int oo = o - 16; int base = (oo >> 2) * 16 + (oo & 3);
            val = s->xs[base][c] + s->xs[base + 4][c] + s->xs[base + 8][c] + s->xs[base + 12][c];
        } else {                    // mean over k; (o-32) = i*4+j
            int oo = o - 32; int base = (oo >> 2) * 16 + (oo & 3) * 4;
            val = s->xs[base][c] + s->xs[base + 1][c] + s->xs[base + 2][c] + s->xs[base + 3][c];
        }
        outb[o * 32 + c] = val * 0.25f;
    }
}

extern "C" void kernel_launch(void* const* d_in, const int* in_sizes, int n_in,
                              void* d_out, int out_size) {
    const float* xx        = (const float*)d_in[0];
    const float* ss        = (const float*)d_in[1];
    const float* W_f       = (const float*)d_in[2];
    const float* b_f       = (const float*)d_in[3];
    const float* conv_w    = (const float*)d_in[4];
    const float* conv_root = (const float*)d_in[5];
    const float* conv_bias = (const float*)d_in[6];
    const float* ln_g      = (const float*)d_in[7];
    const float* ln_b      = (const float*)d_in[8];
    // d_in[9]/d_in[10] (src/dst) unused: aggregation has a closed form.

    const int B = in_sizes[1];

    cudaFuncSetAttribute(gnn_frame0_kernel,
                         cudaFuncAttributeMaxDynamicSharedMemorySize,
                         (int)sizeof(Smem));
    gnn_frame0_kernel<<<B, TPB, sizeof(Smem)>>>(
        xx, ss, W_f, b_f, conv_w, conv_root, conv_bias, ln_g, ln_b,
        (float*)d_out);
}